// round 12
// baseline (speedup 1.0000x reference)
#include <cuda_runtime.h>
#include <math.h>

// Problem-fixed dims
#define NN 100000
#define IN_X 32
#define IN_E 64
#define HID 128
#define OUT 64

// ---- folded weights (computed by k_prep every launch; deterministic) ----
__device__ __align__(16) float g_W0l[IN_X * HID];  // W0 @ W1l
__device__ __align__(16) float g_W0r[IN_X * HID];  // W0 @ W1r
__device__ __align__(16) float g_c0l[HID];         // b0 @ W1l (gated by cnt>0)
__device__ __align__(16) float g_c1[HID];          // b1l + b0 @ W1r
__device__ __align__(16) float g_val[HID];         // W2l @ Wp[0:64]
__device__ __align__(16) float g_vbl[HID];         // W2l @ Wp[64:128]
__device__ __align__(16) float g_var[HID];         // W2r @ Wp[0:64]
__device__ __align__(16) float g_vbr[HID];         // W2r @ Wp[64:128]
__device__ float g_cab[2];   // b2l.Wpa + bp, b2l.Wpb   (bp folded in)

// ---- per-node scratch ----
__device__ __align__(16) float g_ssumx[NN * IN_X]; // scatter of raw x
__device__ __align__(16) float g_cnt[NN];
__device__ __align__(16) float g_pq[2 * NN];       // p,q  -> scatter source
__device__ __align__(16) float g_r[2 * NN];        // ra,rb (self term)
__device__ __align__(16) float g_spq[2 * NN];      // scattered sums of p,q
__device__ __align__(16) float g_ab[2 * NN];       // final per-node scalars

// ---------------------------------------------------------------------------
// Prep + zero fused: blocks 0-3 fold weights; blocks >=4 zero accumulators.
// ---------------------------------------------------------------------------
__global__ void k_prep_zero(const float* __restrict__ W0, const float* __restrict__ b0,
                            const float* __restrict__ W1l, const float* __restrict__ b1l,
                            const float* __restrict__ W1r,
                            const float* __restrict__ W2l, const float* __restrict__ b2l,
                            const float* __restrict__ W2r,
                            const float* __restrict__ Wp, const float* __restrict__ bp,
                            int N) {
    int b = blockIdx.x;
    int j = threadIdx.x;   // 0..127
    if (b >= 4) {
        int i = (b - 4) * 128 + j;
        int stride = (gridDim.x - 4) * 128;
        int n1 = (N * IN_X) / 4;
        float4 z = make_float4(0.f, 0.f, 0.f, 0.f);
        float4* p1 = reinterpret_cast<float4*>(g_ssumx);
        for (int k = i; k < n1; k += stride) p1[k] = z;
        for (int k = i; k < N; k += stride) g_cnt[k] = 0.f;
        float2* p2 = reinterpret_cast<float2*>(g_spq);
        float2 z2 = make_float2(0.f, 0.f);
        for (int k = i; k < N; k += stride) p2[k] = z2;
        return;
    }
    if (b == 0) {
        for (int k = 0; k < IN_X; k++) {
            float s = 0.f;
            for (int m = 0; m < IN_E; m++) s += W0[k * IN_E + m] * W1l[m * HID + j];
            g_W0l[k * HID + j] = s;
        }
        float s = 0.f;
        for (int m = 0; m < IN_E; m++) s += b0[m] * W1l[m * HID + j];
        g_c0l[j] = s;
    } else if (b == 1) {
        for (int k = 0; k < IN_X; k++) {
            float s = 0.f;
            for (int m = 0; m < IN_E; m++) s += W0[k * IN_E + m] * W1r[m * HID + j];
            g_W0r[k * HID + j] = s;
        }
        float s = 0.f;
        for (int m = 0; m < IN_E; m++) s += b0[m] * W1r[m * HID + j];
        g_c1[j] = b1l[j] + s;
    } else if (b == 2) {
        float sa = 0.f, sb = 0.f;
        for (int t = 0; t < OUT; t++) {
            float w = W2l[j * OUT + t];
            sa += w * Wp[t];
            sb += w * Wp[OUT + t];
        }
        g_val[j] = sa; g_vbl[j] = sb;
        if (j == 0) {
            float ca = 0.f, cb = 0.f;
            for (int t = 0; t < OUT; t++) { ca += b2l[t] * Wp[t]; cb += b2l[t] * Wp[OUT + t]; }
            g_cab[0] = ca + bp[0];
            g_cab[1] = cb;
        }
    } else {
        float sa = 0.f, sb = 0.f;
        for (int t = 0; t < OUT; t++) {
            float w = W2r[j * OUT + t];
            sa += w * Wp[t];
            sb += w * Wp[OUT + t];
        }
        g_var[j] = sa; g_vbr[j] = sb;
    }
}

// ---------------------------------------------------------------------------
// Vector no-return reductions (sm_90+)
// ---------------------------------------------------------------------------
__device__ __forceinline__ void red_add_v4(float* p, float4 v) {
    asm volatile("red.global.add.v4.f32 [%0], {%1, %2, %3, %4};"
                 :: "l"(p), "f"(v.x), "f"(v.y), "f"(v.z), "f"(v.w) : "memory");
}
__device__ __forceinline__ void red_add_v2(float* p, float2 v) {
    asm volatile("red.global.add.v2.f32 [%0], {%1, %2};"
                 :: "l"(p), "f"(v.x), "f"(v.y) : "memory");
}

// ---------------------------------------------------------------------------
// Scatter 1: ssumx[dst] += x[src] (32-dim, 8 threads/edge), cnt[dst] += 1
// ---------------------------------------------------------------------------
__global__ void k_scatter1(const float* __restrict__ x,
                           const int* __restrict__ src,
                           const int* __restrict__ dst, int E) {
    int gid = blockIdx.x * blockDim.x + threadIdx.x;
    int e = gid >> 3;
    int c = gid & 7;
    if (e >= E) return;
    int s = src[e];
    int d = dst[e];
    float4 v = *reinterpret_cast<const float4*>(x + (size_t)s * IN_X + c * 4);
    red_add_v4(g_ssumx + (size_t)d * IN_X + c * 4, v);
    if (c == 0) atomicAdd(g_cnt + d, 1.0f);
}

// ---------------------------------------------------------------------------
// SAGE1 (folded), persistent-tile version: one wave of blocks; weights staged
// ONCE per block; each block grid-strides over 32-node tiles. Per-tile body
// is the measured-best R5 code.
//   h1 = relu( meanx @ W0l + flag*c0l + c1 + x @ W0r )   (in registers)
//   p=h1.val, q=h1.vbl -> g_pq ;  ra=h1.var, rb=h1.vbr -> g_r
// ---------------------------------------------------------------------------
#define S1_NODES 32
#define S1_GRID 740   // 148 SMs x 5 blocks (smem-limited occupancy), one wave
__global__ void __launch_bounds__(128) k_sage1(const float* __restrict__ x, int N) {
    __shared__ float4 sWl[IN_X][32];     // [k][lane] 16 KB
    __shared__ float4 sWr[IN_X][32];     // 16 KB
    __shared__ float smx[32][IN_X];      // mean-agg features, 4 KB
    __shared__ float ssx[32][IN_X];      // self features, 4 KB
    __shared__ float sinv[32];
    __shared__ float sflag[32];

    int tid = threadIdx.x;
    int lane = tid & 31, wid = tid >> 5;

    // stage folded weights ONCE per block (1024 float4 each)
    {
        const float4* Wl4 = reinterpret_cast<const float4*>(g_W0l);
        const float4* Wr4 = reinterpret_cast<const float4*>(g_W0r);
        for (int i = tid; i < IN_X * 32; i += 128) {
            sWl[i >> 5][i & 31] = Wl4[i];
            sWr[i >> 5][i & 31] = Wr4[i];
        }
    }

    // epilogue constants (loop-invariant)
    float4 c1v  = reinterpret_cast<const float4*>(g_c1)[lane];
    float4 c0v  = reinterpret_cast<const float4*>(g_c0l)[lane];
    float4 valv = reinterpret_cast<const float4*>(g_val)[lane];
    float4 vblv = reinterpret_cast<const float4*>(g_vbl)[lane];
    float4 varv = reinterpret_cast<const float4*>(g_var)[lane];
    float4 vbrv = reinterpret_cast<const float4*>(g_vbr)[lane];

    int n_tiles = (N + S1_NODES - 1) / S1_NODES;
    int nb = wid * 8;   // this warp's first node (in-tile)

    for (int tile = blockIdx.x; tile < n_tiles; tile += S1_GRID) {
        int n0 = tile * S1_NODES;

        __syncthreads();   // weights ready (1st iter); prior compute done (later)

        // stage per-node cnt
        if (tid < 32) {
            float c = (n0 + tid < N) ? g_cnt[n0 + tid] : 0.f;
            sinv[tid]  = 1.0f / fmaxf(c, 1.0f);
            sflag[tid] = (c > 0.f) ? 1.0f : 0.0f;
        }
        __syncthreads();

        // stage node features: 32 nodes x 8 float4 per array
        for (int i = tid; i < 32 * 8; i += 128) {
            int n = i >> 3, k4 = (i & 7) * 4;
            int row = n0 + n;
            float4 vm = make_float4(0.f, 0.f, 0.f, 0.f);
            float4 vs = vm;
            if (row < N) {
                float inv = sinv[n];
                vm = *reinterpret_cast<const float4*>(g_ssumx + (size_t)row * IN_X + k4);
                vm.x *= inv; vm.y *= inv; vm.z *= inv; vm.w *= inv;
                vs = *reinterpret_cast<const float4*>(x + (size_t)row * IN_X + k4);
            }
            *reinterpret_cast<float4*>(&smx[n][k4]) = vm;
            *reinterpret_cast<float4*>(&ssx[n][k4]) = vs;
        }
        __syncthreads();

        float4 acc[8];
#pragma unroll
        for (int n = 0; n < 8; n++) acc[n] = make_float4(0.f, 0.f, 0.f, 0.f);

#pragma unroll 2
        for (int k = 0; k < IN_X; k += 4) {
            float4 wl0 = sWl[k + 0][lane];
            float4 wl1 = sWl[k + 1][lane];
            float4 wl2 = sWl[k + 2][lane];
            float4 wl3 = sWl[k + 3][lane];
            float4 wr0 = sWr[k + 0][lane];
            float4 wr1 = sWr[k + 1][lane];
            float4 wr2 = sWr[k + 2][lane];
            float4 wr3 = sWr[k + 3][lane];
#pragma unroll
            for (int n = 0; n < 8; n++) {
                float4 a = *reinterpret_cast<const float4*>(&smx[nb + n][k]);   // broadcast
                float4 h = *reinterpret_cast<const float4*>(&ssx[nb + n][k]);   // broadcast
                acc[n].x += a.x * wl0.x + a.y * wl1.x + a.z * wl2.x + a.w * wl3.x
                          + h.x * wr0.x + h.y * wr1.x + h.z * wr2.x + h.w * wr3.x;
                acc[n].y += a.x * wl0.y + a.y * wl1.y + a.z * wl2.y + a.w * wl3.y
                          + h.x * wr0.y + h.y * wr1.y + h.z * wr2.y + h.w * wr3.y;
                acc[n].z += a.x * wl0.z + a.y * wl1.z + a.z * wl2.z + a.w * wl3.z
                          + h.x * wr0.z + h.y * wr1.z + h.z * wr2.z + h.w * wr3.z;
                acc[n].w += a.x * wl0.w + a.y * wl1.w + a.z * wl2.w + a.w * wl3.w
                          + h.x * wr0.w + h.y * wr1.w + h.z * wr2.w + h.w * wr3.w;
            }
        }

        // epilogue: bias + relu + 4 scalar projections per node, warp-reduced
#pragma unroll
        for (int n = 0; n < 8; n++) {
            float flag = sflag[nb + n];
            float hx = fmaxf(acc[n].x + c1v.x + flag * c0v.x, 0.f);
            float hy = fmaxf(acc[n].y + c1v.y + flag * c0v.y, 0.f);
            float hz = fmaxf(acc[n].z + c1v.z + flag * c0v.z, 0.f);
            float hw = fmaxf(acc[n].w + c1v.w + flag * c0v.w, 0.f);
            float pa = hx * valv.x + hy * valv.y + hz * valv.z + hw * valv.w;
            float pb = hx * vblv.x + hy * vblv.y + hz * vblv.z + hw * vblv.w;
            float ra = hx * varv.x + hy * varv.y + hz * varv.z + hw * varv.w;
            float rb = hx * vbrv.x + hy * vbrv.y + hz * vbrv.z + hw * vbrv.w;
#pragma unroll
            for (int o = 16; o > 0; o >>= 1) {
                pa += __shfl_down_sync(0xffffffffu, pa, o);
                pb += __shfl_down_sync(0xffffffffu, pb, o);
                ra += __shfl_down_sync(0xffffffffu, ra, o);
                rb += __shfl_down_sync(0xffffffffu, rb, o);
            }
            int row = n0 + nb + n;
            if (lane == 0 && row < N) {
                *reinterpret_cast<float2*>(g_pq + 2 * (size_t)row) = make_float2(pa, pb);
                *reinterpret_cast<float2*>(g_r  + 2 * (size_t)row) = make_float2(ra, rb);
            }
        }
    }
}

// ---------------------------------------------------------------------------
// Scatter 2 (scalar): spq[dst] += pq[src]   — one thread/edge, 8B red.
// ---------------------------------------------------------------------------
__global__ void k_scatter2(const int* __restrict__ src,
                           const int* __restrict__ dst, int E) {
    int e = blockIdx.x * blockDim.x + threadIdx.x;
    if (e >= E) return;
    int s = src[e];
    int d = dst[e];
    float2 v = *reinterpret_cast<const float2*>(g_pq + 2 * (size_t)s);
    red_add_v2(g_spq + 2 * (size_t)d, v);
}

// ---------------------------------------------------------------------------
// Finish: a = spq.x/max(cnt,1) + cab.x + ra ;  b = spq.y/max(cnt,1) + cab.y + rb
// ---------------------------------------------------------------------------
__global__ void k_finish(int N) {
    int n = blockIdx.x * blockDim.x + threadIdx.x;
    if (n >= N) return;
    float inv = 1.0f / fmaxf(g_cnt[n], 1.0f);
    float2 spq = *reinterpret_cast<const float2*>(g_spq + 2 * (size_t)n);
    float2 r   = *reinterpret_cast<const float2*>(g_r   + 2 * (size_t)n);
    float2 ab;
    ab.x = spq.x * inv + g_cab[0] + r.x;
    ab.y = spq.y * inv + g_cab[1] + r.y;
    *reinterpret_cast<float2*>(g_ab + 2 * (size_t)n) = ab;
}

// ---------------------------------------------------------------------------
// Pred: raw[e] = a[src] + b[dst]; out = {raw, sigmoid(raw)}. 2 edges/thread.
// ---------------------------------------------------------------------------
__global__ void k_pred(const int* __restrict__ src,
                       const int* __restrict__ dst,
                       float* __restrict__ out, int E) {
    int t = blockIdx.x * blockDim.x + threadIdx.x;
    int e0 = t * 2;
    if (e0 >= E) return;
    if (e0 + 1 < E) {
        int2 s2 = *reinterpret_cast<const int2*>(src + e0);
        int2 d2 = *reinterpret_cast<const int2*>(dst + e0);
        float r0 = g_ab[2 * (size_t)s2.x] + g_ab[2 * (size_t)d2.x + 1];
        float r1 = g_ab[2 * (size_t)s2.y] + g_ab[2 * (size_t)d2.y + 1];
        *reinterpret_cast<float2*>(out + e0) = make_float2(r0, r1);
        float g0 = 1.0f / (1.0f + __expf(-r0));
        float g1 = 1.0f / (1.0f + __expf(-r1));
        *reinterpret_cast<float2*>(out + (size_t)E + e0) = make_float2(g0, g1);
    } else {
        float r0 = g_ab[2 * (size_t)src[e0]] + g_ab[2 * (size_t)dst[e0] + 1];
        out[e0] = r0;
        out[(size_t)E + e0] = 1.0f / (1.0f + __expf(-r0));
    }
}

// ---------------------------------------------------------------------------
// Launch
// ---------------------------------------------------------------------------
extern "C" void kernel_launch(void* const* d_in, const int* in_sizes, int n_in,
                              void* d_out, int out_size) {
    const float* x   = (const float*)d_in[0];
    const int*   ei  = (const int*)d_in[1];
    const float* W0  = (const float*)d_in[2];
    const float* b0  = (const float*)d_in[3];
    const float* W1l = (const float*)d_in[4];
    const float* b1l = (const float*)d_in[5];
    const float* W1r = (const float*)d_in[6];
    const float* W2l = (const float*)d_in[7];
    const float* b2l = (const float*)d_in[8];
    const float* W2r = (const float*)d_in[9];
    const float* Wp  = (const float*)d_in[10];
    const float* bp  = (const float*)d_in[11];
    float* out = (float*)d_out;

    int N = in_sizes[0] / IN_X;   // 100000
    int E = in_sizes[1] / 2;      // 2000000
    const int* src = ei;
    const int* dst = ei + E;

    k_prep_zero<<<4 + 2368, 128>>>(W0, b0, W1l, b1l, W1r, W2l, b2l, W2r, Wp, bp, N);

    {   // scatter1: 8 threads/edge
        long long t = (long long)E * 8;
        int blocks = (int)((t + 255) / 256);
        k_scatter1<<<blocks, 256>>>(x, src, dst, E);
    }
    k_sage1<<<S1_GRID, 128>>>(x, N);
    k_scatter2<<<(E + 255) / 256, 256>>>(src, dst, E);
    k_finish<<<(N + 255) / 256, 256>>>(N);
    k_pred<<<(E / 2 + 255) / 256, 256>>>(src, dst, out, E);
}

// round 13
// speedup vs baseline: 1.0718x; 1.0718x over previous
#include <cuda_runtime.h>
#include <math.h>

// Problem-fixed dims
#define NN 100000
#define IN_X 32
#define IN_E 64
#define HID 128
#define OUT 64

// ---- folded weights (computed by k_prep every launch; deterministic) ----
__device__ __align__(16) float g_W0l[IN_X * HID];  // W0 @ W1l
__device__ __align__(16) float g_W0r[IN_X * HID];  // W0 @ W1r
__device__ __align__(16) float g_c0l[HID];         // b0 @ W1l (gated by cnt>0)
__device__ __align__(16) float g_c1[HID];          // b1l + b0 @ W1r
__device__ __align__(16) float g_val[HID];         // W2l @ Wp[0:64]
__device__ __align__(16) float g_vbl[HID];         // W2l @ Wp[64:128]
__device__ __align__(16) float g_var[HID];         // W2r @ Wp[0:64]
__device__ __align__(16) float g_vbr[HID];         // W2r @ Wp[64:128]
__device__ float g_cab[2];   // b2l.Wpa + bp, b2l.Wpb   (bp folded in)

// ---- per-node scratch ----
__device__ __align__(16) float g_ssumx[NN * IN_X]; // scatter of raw x
__device__ __align__(16) float g_cnt[NN];
__device__ __align__(16) float g_pq[2 * NN];       // p,q  -> scatter source
__device__ __align__(16) float g_r[2 * NN];        // ra,rb (self term)
__device__ __align__(16) float g_spq[2 * NN];      // scattered sums of p,q
__device__ __align__(16) float g_ab[2 * NN];       // final per-node scalars

// ---------------------------------------------------------------------------
// Prep + zero fused: blocks 0-3 fold weights; blocks >=4 zero accumulators.
// ---------------------------------------------------------------------------
__global__ void k_prep_zero(const float* __restrict__ W0, const float* __restrict__ b0,
                            const float* __restrict__ W1l, const float* __restrict__ b1l,
                            const float* __restrict__ W1r,
                            const float* __restrict__ W2l, const float* __restrict__ b2l,
                            const float* __restrict__ W2r,
                            const float* __restrict__ Wp, const float* __restrict__ bp,
                            int N) {
    int b = blockIdx.x;
    int j = threadIdx.x;   // 0..127
    if (b >= 4) {
        int i = (b - 4) * 128 + j;
        int stride = (gridDim.x - 4) * 128;
        int n1 = (N * IN_X) / 4;
        float4 z = make_float4(0.f, 0.f, 0.f, 0.f);
        float4* p1 = reinterpret_cast<float4*>(g_ssumx);
        for (int k = i; k < n1; k += stride) p1[k] = z;
        for (int k = i; k < N; k += stride) g_cnt[k] = 0.f;
        float2* p2 = reinterpret_cast<float2*>(g_spq);
        float2 z2 = make_float2(0.f, 0.f);
        for (int k = i; k < N; k += stride) p2[k] = z2;
        return;
    }
    if (b == 0) {
        for (int k = 0; k < IN_X; k++) {
            float s = 0.f;
            for (int m = 0; m < IN_E; m++) s += W0[k * IN_E + m] * W1l[m * HID + j];
            g_W0l[k * HID + j] = s;
        }
        float s = 0.f;
        for (int m = 0; m < IN_E; m++) s += b0[m] * W1l[m * HID + j];
        g_c0l[j] = s;
    } else if (b == 1) {
        for (int k = 0; k < IN_X; k++) {
            float s = 0.f;
            for (int m = 0; m < IN_E; m++) s += W0[k * IN_E + m] * W1r[m * HID + j];
            g_W0r[k * HID + j] = s;
        }
        float s = 0.f;
        for (int m = 0; m < IN_E; m++) s += b0[m] * W1r[m * HID + j];
        g_c1[j] = b1l[j] + s;
    } else if (b == 2) {
        float sa = 0.f, sb = 0.f;
        for (int t = 0; t < OUT; t++) {
            float w = W2l[j * OUT + t];
            sa += w * Wp[t];
            sb += w * Wp[OUT + t];
        }
        g_val[j] = sa; g_vbl[j] = sb;
        if (j == 0) {
            float ca = 0.f, cb = 0.f;
            for (int t = 0; t < OUT; t++) { ca += b2l[t] * Wp[t]; cb += b2l[t] * Wp[OUT + t]; }
            g_cab[0] = ca + bp[0];
            g_cab[1] = cb;
        }
    } else {
        float sa = 0.f, sb = 0.f;
        for (int t = 0; t < OUT; t++) {
            float w = W2r[j * OUT + t];
            sa += w * Wp[t];
            sb += w * Wp[OUT + t];
        }
        g_var[j] = sa; g_vbr[j] = sb;
    }
}

// ---------------------------------------------------------------------------
// Vector no-return reductions (sm_90+)
// ---------------------------------------------------------------------------
__device__ __forceinline__ void red_add_v4(float* p, float4 v) {
    asm volatile("red.global.add.v4.f32 [%0], {%1, %2, %3, %4};"
                 :: "l"(p), "f"(v.x), "f"(v.y), "f"(v.z), "f"(v.w) : "memory");
}
__device__ __forceinline__ void red_add_v2(float* p, float2 v) {
    asm volatile("red.global.add.v2.f32 [%0], {%1, %2};"
                 :: "l"(p), "f"(v.x), "f"(v.y) : "memory");
}

// ---------------------------------------------------------------------------
// Scatter 1: ssumx[dst] += x[src] (32-dim, 8 threads/edge), cnt[dst] += 1
// ---------------------------------------------------------------------------
__global__ void k_scatter1(const float* __restrict__ x,
                           const int* __restrict__ src,
                           const int* __restrict__ dst, int E) {
    int gid = blockIdx.x * blockDim.x + threadIdx.x;
    int e = gid >> 3;
    int c = gid & 7;
    if (e >= E) return;
    int s = src[e];
    int d = dst[e];
    float4 v = *reinterpret_cast<const float4*>(x + (size_t)s * IN_X + c * 4);
    red_add_v4(g_ssumx + (size_t)d * IN_X + c * 4, v);
    if (c == 0) atomicAdd(g_cnt + d, 1.0f);
}

// ---------------------------------------------------------------------------
// SAGE1 (folded), shuffle-free inner loop — measured-best configuration:
//   h1 = relu( meanx @ W0l + flag*c0l + c1 + x @ W0r )   (in registers)
//   p=h1.val, q=h1.vbl -> g_pq ;  ra=h1.var, rb=h1.vbr -> g_r
// Block = 128 thr / 4 warps / 32 nodes. Warp owns 8 nodes; lane owns 4 cols.
// ---------------------------------------------------------------------------
#define S1_NODES 32
__global__ void __launch_bounds__(128) k_sage1(const float* __restrict__ x, int N) {
    __shared__ float4 sWl[IN_X][32];     // [k][lane] 16 KB
    __shared__ float4 sWr[IN_X][32];     // 16 KB
    __shared__ float smx[32][IN_X];      // mean-agg features, 4 KB
    __shared__ float ssx[32][IN_X];      // self features, 4 KB
    __shared__ float sinv[32];
    __shared__ float sflag[32];

    int tid = threadIdx.x;
    int lane = tid & 31, wid = tid >> 5;
    int n0 = blockIdx.x * 32;

    // stage folded weights (1024 float4 each)
    {
        const float4* Wl4 = reinterpret_cast<const float4*>(g_W0l);
        const float4* Wr4 = reinterpret_cast<const float4*>(g_W0r);
        for (int i = tid; i < IN_X * 32; i += 128) {
            sWl[i >> 5][i & 31] = Wl4[i];
            sWr[i >> 5][i & 31] = Wr4[i];
        }
    }
    // stage per-node cnt
    if (tid < 32) {
        float c = (n0 + tid < N) ? g_cnt[n0 + tid] : 0.f;
        sinv[tid]  = 1.0f / fmaxf(c, 1.0f);
        sflag[tid] = (c > 0.f) ? 1.0f : 0.0f;
    }
    __syncthreads();

    // stage node features: 32 nodes x 8 float4 per array
    for (int i = tid; i < 32 * 8; i += 128) {
        int n = i >> 3, k4 = (i & 7) * 4;
        int row = n0 + n;
        float4 vm = make_float4(0.f, 0.f, 0.f, 0.f);
        float4 vs = vm;
        if (row < N) {
            float inv = sinv[n];
            vm = *reinterpret_cast<const float4*>(g_ssumx + (size_t)row * IN_X + k4);
            vm.x *= inv; vm.y *= inv; vm.z *= inv; vm.w *= inv;
            vs = *reinterpret_cast<const float4*>(x + (size_t)row * IN_X + k4);
        }
        *reinterpret_cast<float4*>(&smx[n][k4]) = vm;
        *reinterpret_cast<float4*>(&ssx[n][k4]) = vs;
    }
    __syncthreads();

    int nb = wid * 8;   // this warp's first node (in-block)
    float4 acc[8];
#pragma unroll
    for (int n = 0; n < 8; n++) acc[n] = make_float4(0.f, 0.f, 0.f, 0.f);

#pragma unroll 2
    for (int k = 0; k < IN_X; k += 4) {
        float4 wl0 = sWl[k + 0][lane];
        float4 wl1 = sWl[k + 1][lane];
        float4 wl2 = sWl[k + 2][lane];
        float4 wl3 = sWl[k + 3][lane];
        float4 wr0 = sWr[k + 0][lane];
        float4 wr1 = sWr[k + 1][lane];
        float4 wr2 = sWr[k + 2][lane];
        float4 wr3 = sWr[k + 3][lane];
#pragma unroll
        for (int n = 0; n < 8; n++) {
            float4 a = *reinterpret_cast<const float4*>(&smx[nb + n][k]);   // broadcast
            float4 h = *reinterpret_cast<const float4*>(&ssx[nb + n][k]);   // broadcast
            acc[n].x += a.x * wl0.x + a.y * wl1.x + a.z * wl2.x + a.w * wl3.x
                      + h.x * wr0.x + h.y * wr1.x + h.z * wr2.x + h.w * wr3.x;
            acc[n].y += a.x * wl0.y + a.y * wl1.y + a.z * wl2.y + a.w * wl3.y
                      + h.x * wr0.y + h.y * wr1.y + h.z * wr2.y + h.w * wr3.y;
            acc[n].z += a.x * wl0.z + a.y * wl1.z + a.z * wl2.z + a.w * wl3.z
                      + h.x * wr0.z + h.y * wr1.z + h.z * wr2.z + h.w * wr3.z;
            acc[n].w += a.x * wl0.w + a.y * wl1.w + a.z * wl2.w + a.w * wl3.w
                      + h.x * wr0.w + h.y * wr1.w + h.z * wr2.w + h.w * wr3.w;
        }
    }

    // epilogue: bias + relu + 4 scalar projections per node, warp-reduced
    float4 c1v  = reinterpret_cast<const float4*>(g_c1)[lane];
    float4 c0v  = reinterpret_cast<const float4*>(g_c0l)[lane];
    float4 valv = reinterpret_cast<const float4*>(g_val)[lane];
    float4 vblv = reinterpret_cast<const float4*>(g_vbl)[lane];
    float4 varv = reinterpret_cast<const float4*>(g_var)[lane];
    float4 vbrv = reinterpret_cast<const float4*>(g_vbr)[lane];

#pragma unroll
    for (int n = 0; n < 8; n++) {
        float flag = sflag[nb + n];
        float hx = fmaxf(acc[n].x + c1v.x + flag * c0v.x, 0.f);
        float hy = fmaxf(acc[n].y + c1v.y + flag * c0v.y, 0.f);
        float hz = fmaxf(acc[n].z + c1v.z + flag * c0v.z, 0.f);
        float hw = fmaxf(acc[n].w + c1v.w + flag * c0v.w, 0.f);
        float pa = hx * valv.x + hy * valv.y + hz * valv.z + hw * valv.w;
        float pb = hx * vblv.x + hy * vblv.y + hz * vblv.z + hw * vblv.w;
        float ra = hx * varv.x + hy * varv.y + hz * varv.z + hw * varv.w;
        float rb = hx * vbrv.x + hy * vbrv.y + hz * vbrv.z + hw * vbrv.w;
#pragma unroll
        for (int o = 16; o > 0; o >>= 1) {
            pa += __shfl_down_sync(0xffffffffu, pa, o);
            pb += __shfl_down_sync(0xffffffffu, pb, o);
            ra += __shfl_down_sync(0xffffffffu, ra, o);
            rb += __shfl_down_sync(0xffffffffu, rb, o);
        }
        int row = n0 + nb + n;
        if (lane == 0 && row < N) {
            *reinterpret_cast<float2*>(g_pq + 2 * (size_t)row) = make_float2(pa, pb);
            *reinterpret_cast<float2*>(g_r  + 2 * (size_t)row) = make_float2(ra, rb);
        }
    }
}

// ---------------------------------------------------------------------------
// Scatter 2 (scalar): spq[dst] += pq[src]   — one thread/edge, 8B red.
// ---------------------------------------------------------------------------
__global__ void k_scatter2(const int* __restrict__ src,
                           const int* __restrict__ dst, int E) {
    int e = blockIdx.x * blockDim.x + threadIdx.x;
    if (e >= E) return;
    int s = src[e];
    int d = dst[e];
    float2 v = *reinterpret_cast<const float2*>(g_pq + 2 * (size_t)s);
    red_add_v2(g_spq + 2 * (size_t)d, v);
}

// ---------------------------------------------------------------------------
// Finish: a = spq.x/max(cnt,1) + cab.x + ra ;  b = spq.y/max(cnt,1) + cab.y + rb
// ---------------------------------------------------------------------------
__global__ void k_finish(int N) {
    int n = blockIdx.x * blockDim.x + threadIdx.x;
    if (n >= N) return;
    float inv = 1.0f / fmaxf(g_cnt[n], 1.0f);
    float2 spq = *reinterpret_cast<const float2*>(g_spq + 2 * (size_t)n);
    float2 r   = *reinterpret_cast<const float2*>(g_r   + 2 * (size_t)n);
    float2 ab;
    ab.x = spq.x * inv + g_cab[0] + r.x;
    ab.y = spq.y * inv + g_cab[1] + r.y;
    *reinterpret_cast<float2*>(g_ab + 2 * (size_t)n) = ab;
}

// ---------------------------------------------------------------------------
// Pred: raw[e] = a[src] + b[dst]; out = {raw, sigmoid(raw)}. 4 edges/thread.
// ---------------------------------------------------------------------------
__global__ void k_pred(const int* __restrict__ src,
                       const int* __restrict__ dst,
                       float* __restrict__ out, int E) {
    int t = blockIdx.x * blockDim.x + threadIdx.x;
    int e0 = t * 4;
    if (e0 >= E) return;
    if (e0 + 3 < E) {
        int4 s4 = *reinterpret_cast<const int4*>(src + e0);
        int4 d4 = *reinterpret_cast<const int4*>(dst + e0);
        float r0 = g_ab[2 * (size_t)s4.x] + g_ab[2 * (size_t)d4.x + 1];
        float r1 = g_ab[2 * (size_t)s4.y] + g_ab[2 * (size_t)d4.y + 1];
        float r2 = g_ab[2 * (size_t)s4.z] + g_ab[2 * (size_t)d4.z + 1];
        float r3 = g_ab[2 * (size_t)s4.w] + g_ab[2 * (size_t)d4.w + 1];
        *reinterpret_cast<float4*>(out + e0) = make_float4(r0, r1, r2, r3);
        float g0 = 1.0f / (1.0f + __expf(-r0));
        float g1 = 1.0f / (1.0f + __expf(-r1));
        float g2 = 1.0f / (1.0f + __expf(-r2));
        float g3 = 1.0f / (1.0f + __expf(-r3));
        *reinterpret_cast<float4*>(out + (size_t)E + e0) = make_float4(g0, g1, g2, g3);
    } else {
        for (int e = e0; e < E; e++) {
            float r0 = g_ab[2 * (size_t)src[e]] + g_ab[2 * (size_t)dst[e] + 1];
            out[e] = r0;
            out[(size_t)E + e] = 1.0f / (1.0f + __expf(-r0));
        }
    }
}

// ---------------------------------------------------------------------------
// Launch
// ---------------------------------------------------------------------------
extern "C" void kernel_launch(void* const* d_in, const int* in_sizes, int n_in,
                              void* d_out, int out_size) {
    const float* x   = (const float*)d_in[0];
    const int*   ei  = (const int*)d_in[1];
    const float* W0  = (const float*)d_in[2];
    const float* b0  = (const float*)d_in[3];
    const float* W1l = (const float*)d_in[4];
    const float* b1l = (const float*)d_in[5];
    const float* W1r = (const float*)d_in[6];
    const float* W2l = (const float*)d_in[7];
    const float* b2l = (const float*)d_in[8];
    const float* W2r = (const float*)d_in[9];
    const float* Wp  = (const float*)d_in[10];
    const float* bp  = (const float*)d_in[11];
    float* out = (float*)d_out;

    int N = in_sizes[0] / IN_X;   // 100000
    int E = in_sizes[1] / 2;      // 2000000
    const int* src = ei;
    const int* dst = ei + E;

    k_prep_zero<<<4 + 2368, 128>>>(W0, b0, W1l, b1l, W1r, W2l, b2l, W2r, Wp, bp, N);

    {   // scatter1: 8 threads/edge
        long long t = (long long)E * 8;
        int blocks = (int)((t + 255) / 256);
        k_scatter1<<<blocks, 256>>>(x, src, dst, E);
    }
    k_sage1<<<(N + S1_NODES - 1) / S1_NODES, 128>>>(x, N);
    k_scatter2<<<(E + 255) / 256, 256>>>(src, dst, E);
    k_finish<<<(N + 255) / 256, 256>>>(N);
    k_pred<<<(E / 4 + 255) / 256, 256>>>(src, dst, out, E);
}